// round 10
// baseline (speedup 1.0000x reference)
#include <cuda_runtime.h>
#include <cuda_fp16.h>

#define ACTIVE     32
#define HIDDEN     256
#define ACCDIM     512
#define NTHREADS   256
#define NWARPS     (NTHREADS / 32)
#define INPUTSZ    40960

#define STG_ROWS   4                  // rows per chunk
#define STG_BUFS   2                  // double buffer
#define ROWB       512                // bytes per fp16 row
#define STG_WARP_BYTES (STG_BUFS * STG_ROWS * ROWB)   // 4 KB per warp

__device__ __forceinline__ unsigned int h2_to_u32(__half2 h) {
    return *reinterpret_cast<unsigned int*>(&h);
}
__device__ __forceinline__ __half2 u32_to_h2(unsigned int u) {
    return *reinterpret_cast<__half2*>(&u);
}
__device__ __forceinline__ float satf(float x) { return __saturatef(x); }

__device__ __forceinline__ void fma_f32x2(unsigned long long& d,
                                          unsigned long long a,
                                          unsigned long long b) {
    asm("fma.rn.f32x2 %0, %1, %2, %0;" : "+l"(d) : "l"(a), "l"(b));
}
__device__ __forceinline__ unsigned long long pack_f32x2(float lo, float hi) {
    unsigned long long v;
    asm("mov.b64 %0, {%1, %2};" : "=l"(v)
        : "r"(__float_as_uint(lo)), "r"(__float_as_uint(hi)));
    return v;
}
__device__ __forceinline__ float f32x2_hsum(unsigned long long v) {
    unsigned int lo, hi;
    asm("mov.b64 {%0,%1}, %2;" : "=r"(lo), "=r"(hi) : "l"(v));
    return __uint_as_float(lo) + __uint_as_float(hi);
}

// async 16B copy, L1-bypass (LDGSTS.E.BYPASS.128)
__device__ __forceinline__ void cp_async_cg16(unsigned int smem_addr,
                                              const void* gptr) {
    asm volatile("cp.async.cg.shared.global [%0], [%1], 16;\n"
                 :: "r"(smem_addr), "l"(gptr));
}
__device__ __forceinline__ void cp_async_commit() {
    asm volatile("cp.async.commit_group;\n" ::: "memory");
}
__device__ __forceinline__ void cp_async_wait1() {
    asm volatile("cp.async.wait_group 1;\n" ::: "memory");
}
__device__ __forceinline__ void cp_async_wait0() {
    asm volatile("cp.async.wait_group 0;\n" ::: "memory");
}

// fp16 shadow of ft_w: 40960 rows x 256 halves = 512B/row = 32 uint4/row
__device__ uint4 g_ftw_h[INPUTSZ * 32];
// l1_w transposed+packed fp16: [j4][k] -> 4 halves as uint2
__device__ uint2 g_l1w_h[128 * 32];

// dynamic smem (per CTA):
//   sh_w1h : 128*32 uint2  (32 KB)  packed fp16 L1 weights
//   sh_l2t : 32*32  float  ( 4 KB)  l2_w transposed [j][k]
//   sh_acc : NWARPS*2*512 float (32 KB)
//   sh_stg : NWARPS*4KB    (32 KB)  gather staging
#define SMEM_W1H_U2  (128 * 32)
#define SMEM_L2T     (32 * 32)
#define SMEM_ACC     (NWARPS * 2 * ACCDIM)
#define SMEM_STG_F   (NWARPS * STG_WARP_BYTES / 4)
#define SMEM_BYTES   (SMEM_W1H_U2 * 8 + (SMEM_L2T + SMEM_ACC + SMEM_STG_F) * 4)

// ---------- merged prepass (one launch; every call; deterministic) ----------
__global__ void prepass_kernel(const float* __restrict__ ft_w,
                               const float* __restrict__ l1_w, int n_u4)
{
    int i = blockIdx.x * blockDim.x + threadIdx.x;
    if (i < n_u4) {
        const float4* src = (const float4*)ft_w;
        float4 a = src[2 * i];
        float4 b = src[2 * i + 1];
        uint4 o;
        o.x = h2_to_u32(__floats2half2_rn(a.x, a.y));
        o.y = h2_to_u32(__floats2half2_rn(a.z, a.w));
        o.z = h2_to_u32(__floats2half2_rn(b.x, b.y));
        o.w = h2_to_u32(__floats2half2_rn(b.z, b.w));
        g_ftw_h[i] = o;
    }
    if (blockIdx.x == 0) {
        for (int t = threadIdx.x; t < 128 * 32; t += NTHREADS) {
            int j4 = t >> 5, k = t & 31;
            const float* r = l1_w + k * ACCDIM + j4 * 4;
            uint2 o;
            o.x = h2_to_u32(__floats2half2_rn(r[0], r[1]));
            o.y = h2_to_u32(__floats2half2_rn(r[2], r[3]));
            g_l1w_h[t] = o;
        }
    }
}

// ---------- main fused kernel ----------
__global__ __launch_bounds__(NTHREADS, 2)
void nnue_fused_kernel(
    const int*   __restrict__ white_idx,
    const int*   __restrict__ black_idx,
    const float* __restrict__ stm,
    const float* __restrict__ ft_b,
    const float* __restrict__ l2_w,
    const float* __restrict__ l1_b,
    const float* __restrict__ l2_b,
    const float* __restrict__ l3_w,
    const float* __restrict__ l3_b,
    float*       __restrict__ out,
    int B)
{
    extern __shared__ float sm[];
    uint2* sh_w1h = (uint2*)sm;                            // [128][32]
    float* sh_l2t = sm + SMEM_W1H_U2 * 2;                  // [32][32]
    float* sh_acc = sh_l2t + SMEM_L2T;
    float* sh_stg = sh_acc + SMEM_ACC;

    const int tid = threadIdx.x;

    for (int i = tid; i < SMEM_W1H_U2; i += NTHREADS)
        sh_w1h[i] = g_l1w_h[i];
    for (int i = tid; i < SMEM_L2T; i += NTHREADS) {
        int j = i >> 5, k = i & 31;
        sh_l2t[i] = l2_w[k * 32 + j];
    }
    __syncthreads();

    const int lane  = tid & 31;
    const int warp  = tid >> 5;
    const int gwarp = blockIdx.x * NWARPS + warp;
    const int wstride = gridDim.x * NWARPS;

    float4* acc0_4 = (float4*)(sh_acc + warp * 2 * ACCDIM);   // 128 float4
    float4* acc1_4 = acc0_4 + (ACCDIM / 4);
    const ulonglong2* acc0_u2 = (const ulonglong2*)acc0_4;
    const ulonglong2* acc1_u2 = (const ulonglong2*)acc1_4;

    // smem staging addresses (32-bit shared window)
    unsigned int stg_base;
    {
        const void* p = (const void*)(sh_stg + warp * (STG_WARP_BYTES / 4));
        asm("{ .reg .u64 t; cvta.to.shared.u64 t, %1; cvt.u32.u64 %0, t; }"
            : "=r"(stg_base) : "l"(p));
    }

    const float l1b = l1_b[lane];
    const float l2b = l2_b[lane];
    const float l3w = l3_w[lane];
    const float l3b = l3_b[0];
    const float4* ftb4 = (const float4*)ft_b;
    const float4 fbA = ftb4[2 * lane];
    const float4 fbB = ftb4[2 * lane + 1];

    const int G = B >> 1;   // B even

    for (int g = gwarp; g < G; g += wstride) {
        const int p0 = g * 2;
        const int p1 = p0 + 1;

        // 128 rows per pair: chunks 0..7 = p0 white, 8..15 = p0 black,
        // 16..23 = p1 white, 24..31 = p1 black (4 rows/chunk)
        const int* idx_src[4] = {
            white_idx + p0 * ACTIVE, black_idx + p0 * ACTIVE,
            white_idx + p1 * ACTIVE, black_idx + p1 * ACTIVE };

        // fp32 side totals (8 per side), both sides of current position
        float tw[8] = {0,0,0,0,0,0,0,0};
        float tb[8] = {0,0,0,0,0,0,0,0};

        // issue chunk 0
        {
            const int* ip = idx_src[0];
            unsigned int dst = stg_base + lane * 16;
            #pragma unroll
            for (int u = 0; u < STG_ROWS; u++) {
                const int id = __ldg(ip + u);
                cp_async_cg16(dst + u * ROWB, &g_ftw_h[(long)id * 32 + lane]);
            }
            cp_async_commit();
        }

        #pragma unroll 2
        for (int c = 0; c < 32; c++) {
            // issue chunk c+1 into the other buffer
            if (c < 31) {
                const int cn = c + 1;
                const int* ip = idx_src[cn >> 3] + (cn & 7) * STG_ROWS;
                unsigned int dst = stg_base + (cn & 1) * (STG_ROWS * ROWB) + lane * 16;
                #pragma unroll
                for (int u = 0; u < STG_ROWS; u++) {
                    const int id = __ldg(ip + u);
                    cp_async_cg16(dst + u * ROWB, &g_ftw_h[(long)id * 32 + lane]);
                }
                cp_async_commit();
                cp_async_wait1();    // chunk c has landed
            } else {
                cp_async_wait0();    // last chunk
            }

            // consume chunk c: fp16 sum of 4 rows, then fp32 combine
            const unsigned int src = stg_base + (c & 1) * (STG_ROWS * ROWB) + lane * 16;
            __half2 s0 = u32_to_h2(0u), s1 = s0, s2 = s0, s3 = s0;
            #pragma unroll
            for (int u = 0; u < STG_ROWS; u++) {
                unsigned int r0, r1, r2, r3;
                asm volatile("ld.shared.v4.u32 {%0,%1,%2,%3}, [%4];"
                             : "=r"(r0), "=r"(r1), "=r"(r2), "=r"(r3)
                             : "r"(src + u * ROWB));
                s0 = __hadd2(s0, u32_to_h2(r0));
                s1 = __hadd2(s1, u32_to_h2(r1));
                s2 = __hadd2(s2, u32_to_h2(r2));
                s3 = __hadd2(s3, u32_to_h2(r3));
            }
            float* t = ((c >> 3) & 1) ? tb : tw;
            const float2 f0 = __half22float2(s0);
            const float2 f1 = __half22float2(s1);
            const float2 f2 = __half22float2(s2);
            const float2 f3 = __half22float2(s3);
            t[0] += f0.x; t[1] += f0.y; t[2] += f1.x; t[3] += f1.y;
            t[4] += f2.x; t[5] += f2.y; t[6] += f3.x; t[7] += f3.y;

            // finalize a position after its 16 chunks (c==15 -> p0, c==31 -> p1)
            if ((c & 15) == 15) {
                const int pp = c >> 4;
                float4* accp = pp ? acc1_4 : acc0_4;
                const int pos = pp ? p1 : p0;

                float4 cw0 = make_float4(satf(tw[0]+fbA.x), satf(tw[1]+fbA.y),
                                         satf(tw[2]+fbA.z), satf(tw[3]+fbA.w));
                float4 cw1 = make_float4(satf(tw[4]+fbB.x), satf(tw[5]+fbB.y),
                                         satf(tw[6]+fbB.z), satf(tw[7]+fbB.w));
                float4 cb0 = make_float4(satf(tb[0]+fbA.x), satf(tb[1]+fbA.y),
                                         satf(tb[2]+fbA.z), satf(tb[3]+fbA.w));
                float4 cb1 = make_float4(satf(tb[4]+fbB.x), satf(tb[5]+fbB.y),
                                         satf(tb[6]+fbB.z), satf(tb[7]+fbB.w));

                const float s = stm[pos];
                const bool wfirst = (s > 0.5f);
                accp[2*lane]          = wfirst ? cw0 : cb0;
                accp[2*lane + 1]      = wfirst ? cw1 : cb1;
                accp[64 + 2*lane]     = wfirst ? cb0 : cw0;
                accp[64 + 2*lane + 1] = wfirst ? cb1 : cw1;

                #pragma unroll
                for (int q = 0; q < 8; q++) { tw[q] = 0.f; tb[q] = 0.f; }
            }
        }
        __syncwarp();

        // ---- L1: lane k computes output k for both positions ----
        unsigned long long q00 = 0ull, q01 = 0ull;
        unsigned long long q10 = 0ull, q11 = 0ull;
        #pragma unroll 4
        for (int j4 = 0; j4 < 128; j4++) {
            const uint2 wp = sh_w1h[j4 * 32 + lane];       // conflict-free
            const float2 wlo = __half22float2(u32_to_h2(wp.x));
            const float2 whi = __half22float2(u32_to_h2(wp.y));
            const unsigned long long W0 = pack_f32x2(wlo.x, wlo.y);
            const unsigned long long W1 = pack_f32x2(whi.x, whi.y);
            const ulonglong2 A0 = acc0_u2[j4];             // broadcast
            const ulonglong2 A1 = acc1_u2[j4];             // broadcast
            fma_f32x2(q00, A0.x, W0); fma_f32x2(q01, A0.y, W1);
            fma_f32x2(q10, A1.x, W0); fma_f32x2(q11, A1.y, W1);
        }
        const float x1_0 = satf(f32x2_hsum(q00) + f32x2_hsum(q01) + l1b);
        const float x1_1 = satf(f32x2_hsum(q10) + f32x2_hsum(q11) + l1b);
        __syncwarp();

        // ---- L2 + L3 ----
        #pragma unroll
        for (int pp = 0; pp < 2; pp++) {
            const float x1 = pp ? x1_1 : x1_0;
            float s2 = l2b;
            #pragma unroll
            for (int j = 0; j < 32; j++) {
                const float xj = __shfl_sync(0xffffffffu, x1, j);
                s2 += xj * sh_l2t[j * 32 + lane];
            }
            const float x2 = satf(s2);
            float p = x2 * l3w;
            #pragma unroll
            for (int off = 16; off > 0; off >>= 1)
                p += __shfl_xor_sync(0xffffffffu, p, off);
            if (lane == 0)
                out[pp ? p1 : p0] = p + l3b;
        }
    }
}

extern "C" void kernel_launch(void* const* d_in, const int* in_sizes, int n_in,
                              void* d_out, int out_size)
{
    const int*   white_idx = (const int*)  d_in[0];
    const int*   black_idx = (const int*)  d_in[1];
    const float* stm       = (const float*)d_in[2];
    const float* ft_w      = (const float*)d_in[3];
    const float* ft_b      = (const float*)d_in[4];
    const float* l1_w      = (const float*)d_in[5];
    const float* l1_b      = (const float*)d_in[6];
    const float* l2_w      = (const float*)d_in[7];
    const float* l2_b      = (const float*)d_in[8];
    const float* l3_w      = (const float*)d_in[9];
    const float* l3_b      = (const float*)d_in[10];
    float* out = (float*)d_out;

    const int B = in_sizes[0] / ACTIVE;

    const int n_u4 = INPUTSZ * 32;
    prepass_kernel<<<(n_u4 + NTHREADS - 1) / NTHREADS, NTHREADS>>>(ft_w, l1_w, n_u4);

    cudaFuncSetAttribute(nnue_fused_kernel,
                         cudaFuncAttributeMaxDynamicSharedMemorySize,
                         (int)SMEM_BYTES);
    const int grid = 296;   // 2 CTAs/SM on 148 SMs
    nnue_fused_kernel<<<grid, NTHREADS, SMEM_BYTES>>>(
        white_idx, black_idx, stm, ft_b, l2_w,
        l1_b, l2_b, l3_w, l3_b, out, B);
}